// round 4
// baseline (speedup 1.0000x reference)
#include <cuda_runtime.h>
#include <cstdint>
#include <cstddef>

#define FULLMASK 0xFFFFFFFFu

namespace {
constexpr int      HW      = 4096;   // 64*64
constexpr unsigned KSEL    = 409;    // int(0.1 * 4096)
constexpr int      NTHREAD = 512;
constexpr int      NELEM   = 8;      // elements per thread
constexpr int      NWARP   = 16;
constexpr int      CAP     = 64;     // candidate capacity for selected bin
// s-domain cut: s = u<<1 >= bits(1.5f)<<1  <=>  |x| >= 1.5.
// bin >= 1 requires |x| >= 1.50125, so this is a strict superset. ~13% pass.
constexpr unsigned SCUT    = 0x3FC00000u << 1;   // 0x7F800000
}

struct SmemT {
    unsigned hist[256];
    unsigned wsum[NWARP];
    unsigned cnt;
    unsigned sel;       // selected bin (0xFFFFFFFF = none)
    unsigned r2;        // rank within selected bin
    unsigned Ts;        // threshold key (|x| bits << 1)
    unsigned inv_star;  // inverted-index cutoff for exact ties
    unsigned cs[CAP];
    unsigned cinv[CAP];
};

// bin = trunc(|x|*800 - 1200): bin 0 <=> |x| < 1.50125 (6.2 sigma below the
// 409th order statistic of an N(0,1) row), bin >= 255 <=> |x| >= 1.81875
// (7.6 sigma above). Monotone in |x|; the IDENTICAL expression is used in the
// histogram and retrieval passes so bin equality is exact.
__device__ __forceinline__ int bin_of_s(unsigned s) {
    float ax = __uint_as_float(s >> 1);          // |x|
    return (int)fmaf(ax, 800.0f, -1200.0f);
}

// Block-wide total of per-thread count c (broadcast). Fallback path only.
__device__ __forceinline__ unsigned blk_total(SmemT* sm, unsigned c, int lane, int wid) {
    c = __reduce_add_sync(FULLMASK, c);
    __syncthreads();               // protect wsum reuse across calls
    if (lane == 0) sm->wsum[wid] = c;
    __syncthreads();
    unsigned t = 0;
#pragma unroll
    for (int w = 0; w < NWARP; w++) t += sm->wsum[w];
    return t;
}

__global__ void __launch_bounds__(NTHREAD, 3)
topk_sparse_kernel(const float* __restrict__ x, float* __restrict__ y)
{
    __shared__ SmemT sm;
    const int tid  = threadIdx.x;
    const int lane = tid & 31;
    const int wid  = tid >> 5;
    const size_t rowbase = (size_t)blockIdx.x * (HW / 4);
    const uint4* xin  = reinterpret_cast<const uint4*>(x) + rowbase;
    uint4*       yout = reinterpret_cast<uint4*>(y) + rowbase;

    // ---- load row: 8 elements/thread, original bits kept (sign intact) ----
    unsigned u[NELEM];
#pragma unroll
    for (int j = 0; j < 2; j++) {
        uint4 t = xin[tid + j * NTHREAD];
        u[4*j+0] = t.x; u[4*j+1] = t.y; u[4*j+2] = t.z; u[4*j+3] = t.w;
    }
    // element (j,c) at linear idx 4*(tid + j*NTHREAD) + c; inv = 4095 - idx
    const unsigned invbase = 4095u - ((unsigned)tid << 2);

    if (tid < 256) sm.hist[tid] = 0;
    if (tid == 0) { sm.cnt = 0; sm.sel = 0xFFFFFFFFu; }
    __syncthreads();

    // ---- histogram pass: cheap cut first, bin math for ~13% only ----
#pragma unroll
    for (int e = 0; e < NELEM; e++) {
        unsigned s = u[e] << 1;
        if (s >= SCUT) {
            int bin = min(bin_of_s(s), 255);
            if (bin >= 1) atomicAdd(&sm.hist[bin], 1u);
        }
    }
    __syncthreads();

    // ---- descending cumulative scan (threads 0..255, 8 warps) ----
    if (tid < 256) {
        int b = 255 - tid;
        unsigned cb = (b >= 1) ? sm.hist[b] : 0u;   // bin 0 uncounted by design
        unsigned incl = cb;
#pragma unroll
        for (int d = 1; d < 32; d <<= 1) {
            unsigned n = __shfl_up_sync(FULLMASK, incl, d);
            if (lane >= d) incl += n;
        }
        if (lane == 31) sm.wsum[wid] = incl;
    }
    __syncthreads();
    if (tid < 256) {
        int b = 255 - tid;
        unsigned cb = (b >= 1) ? sm.hist[b] : 0u;
        unsigned incl = cb;
#pragma unroll
        for (int d = 1; d < 32; d <<= 1) {
            unsigned n = __shfl_up_sync(FULLMASK, incl, d);
            if (lane >= d) incl += n;
        }
#pragma unroll
        for (int w = 0; w < 8 - 1; w++)
            if (w < wid) incl += sm.wsum[w];
        unsigned excl = incl - cb;
        if (excl < KSEL && KSEL <= incl) { sm.sel = (unsigned)b; sm.r2 = KSEL - excl; }
    }
    __syncthreads();

    // ---- retrieve the (expected ~1-3) candidates of the selected bin ----
    const int sel = (int)sm.sel;
#pragma unroll
    for (int e = 0; e < NELEM; e++) {
        unsigned s = u[e] << 1;
        if (s >= SCUT && bin_of_s(s) == sel) {
            unsigned pos = atomicAdd(&sm.cnt, 1u);
            if (pos < (unsigned)CAP) {
                sm.cs[pos]   = s;
                sm.cinv[pos] = invbase - (unsigned)(((e >> 2) << 11) + (e & 3));
            }
        }
    }
    __syncthreads();

    const bool fb = (sm.sel == 0xFFFFFFFFu) || (sm.sel >= 255u) || (sm.cnt > (unsigned)CAP);
    if (!fb) {
        // ---- exact selection of rank r2 within the bin (ties by index) ----
        const unsigned m2 = sm.cnt;
        const unsigned r2 = sm.r2;
        if ((unsigned)tid < m2) {
            unsigned si = sm.cs[tid], vi = sm.cinv[tid];
            unsigned rank = 0;
            for (unsigned j = 0; j < m2; j++) {
                unsigned sj = sm.cs[j], vj = sm.cinv[j];
                rank += (sj > si || (sj == si && vj > vi)) ? 1u : 0u;
            }
            if (rank == r2 - 1u) { sm.Ts = si; sm.inv_star = vi; }
        }
    } else {
        // ---- exact fallback: bitwise binary search (block-uniform) ----
        unsigned lo = 0;                       // s values are even; bit0 skipped
        for (int bit = 31; bit >= 1; bit--) {
            unsigned T = lo | (1u << bit);
            unsigned c = 0;
#pragma unroll
            for (int e = 0; e < NELEM; e++) c += ((u[e] << 1) >= T) ? 1u : 0u;
            if (blk_total(&sm, c, lane, wid) >= KSEL) lo = T;
        }
        const unsigned Tsf = lo;               // exact KSEL-th largest key
        unsigned cgt = 0;
#pragma unroll
        for (int e = 0; e < NELEM; e++) cgt += ((u[e] << 1) > Tsf) ? 1u : 0u;
        cgt = blk_total(&sm, cgt, lane, wid);
        const unsigned req = KSEL - cgt;       // >= 1 by construction
        unsigned vlo = 0;
        for (int bit = 11; bit >= 0; bit--) {
            unsigned V = vlo | (1u << bit);
            unsigned c = 0;
#pragma unroll
            for (int e = 0; e < NELEM; e++) {
                unsigned inv = invbase - (unsigned)(((e >> 2) << 11) + (e & 3));
                c += (((u[e] << 1) == Tsf) && inv >= V) ? 1u : 0u;
            }
            if (blk_total(&sm, c, lane, wid) >= req) vlo = V;
        }
        if (tid == 0) { sm.Ts = Tsf; sm.inv_star = vlo; }
    }
    __syncthreads();

    const unsigned Ts    = sm.Ts;
    const unsigned istar = sm.inv_star;

    // ---- masked write-back: keep iff strictly above threshold, or equal
    //      with index among the first (tie cutoff encoded in inv_star) ----
#pragma unroll
    for (int j = 0; j < 2; j++) {
        unsigned v[4];
#pragma unroll
        for (int c = 0; c < 4; c++) {
            const int e = 4*j + c;
            const unsigned s   = u[e] << 1;
            const unsigned inv = invbase - (unsigned)((j << 11) + c);
            const bool keep = (s > Ts) || (s == Ts && inv >= istar);
            v[c] = keep ? u[e] : 0u;
        }
        uint4 o; o.x = v[0]; o.y = v[1]; o.z = v[2]; o.w = v[3];
        yout[tid + j * NTHREAD] = o;
    }
}

extern "C" void kernel_launch(void* const* d_in, const int* in_sizes, int n_in,
                              void* d_out, int out_size) {
    const float* x = (const float*)d_in[0];
    float* y = (float*)d_out;
    const int nrows = in_sizes[0] / HW;   // 16384 rows of 4096
    topk_sparse_kernel<<<nrows, NTHREAD>>>(x, y);
}

// round 5
// speedup vs baseline: 2.3448x; 2.3448x over previous
#include <cuda_runtime.h>
#include <cstdint>
#include <cstddef>

#define FULLMASK 0xFFFFFFFFu

namespace {
constexpr int      HW      = 4096;   // 64*64
constexpr unsigned KSEL    = 409;    // int(0.1 * 4096)
constexpr int      NTHREAD = 256;
constexpr int      NWARP   = 8;
constexpr int      CAP     = 64;     // candidate capacity for selected bin
}

struct SmemT {
    uint4    data[HW / 4];   // 16KB row stash (each thread reads only its own words)
    unsigned hist[256];
    unsigned wsum[NWARP];
    unsigned cnt;
    unsigned sel;       // selected bin (0xFFFFFFFF = none)
    unsigned r2;        // rank within selected bin
    unsigned Ts;        // threshold key (|x| bits << 1)
    unsigned inv_star;  // inverted-index cutoff for exact ties
    unsigned cs[CAP];
    unsigned cinv[CAP];
};

// bin = trunc(|x|*800 - 1200): bin 0 <=> |x| < 1.50125 (6.2 sigma below the
// 409th order statistic of an N(0,1) row), bin >= 255 <=> |x| >= 1.81875
// (7.6 sigma above). Monotone in |x|; the IDENTICAL expression is used in the
// histogram and retrieval passes so bin equality is exact.
__device__ __forceinline__ int bin_of(unsigned u) {
    float ax = fabsf(__uint_as_float(u));
    return (int)fmaf(ax, 800.0f, -1200.0f);
}

// Block-wide total of per-thread count c (broadcast). Fallback path only.
__device__ __forceinline__ unsigned blk_total(SmemT* sm, unsigned c, int lane, int wid) {
    c = __reduce_add_sync(FULLMASK, c);
    __syncthreads();               // protect wsum reuse across calls
    if (lane == 0) sm->wsum[wid] = c;
    __syncthreads();
    unsigned t = 0;
#pragma unroll
    for (int w = 0; w < NWARP; w++) t += sm->wsum[w];
    return t;
}

__global__ void __launch_bounds__(NTHREAD, 7)
topk_sparse_kernel(const float* __restrict__ x, float* __restrict__ y)
{
    __shared__ SmemT sm;
    const int tid  = threadIdx.x;
    const int lane = tid & 31;
    const int wid  = tid >> 5;
    const size_t rowbase = (size_t)blockIdx.x * (HW / 4);
    const uint4* xin  = reinterpret_cast<const uint4*>(x) + rowbase;
    uint4*       yout = reinterpret_cast<uint4*>(y) + rowbase;
    // element (j,c) at linear idx 4*tid + 1024*j + c; inv = 4095 - idx
    const unsigned invbase = 4095u - ((unsigned)tid << 2);

    // ---- load row (4 x LDG.128, front-batched for MLP), stash to smem ----
    uint4 t0 = xin[tid];
    uint4 t1 = xin[tid + 256];
    uint4 t2 = xin[tid + 512];
    uint4 t3 = xin[tid + 768];

    sm.hist[tid] = 0;
    if (tid == 0) { sm.cnt = 0; sm.sel = 0xFFFFFFFFu; }

    sm.data[tid]       = t0;
    sm.data[tid + 256] = t1;
    sm.data[tid + 512] = t2;
    sm.data[tid + 768] = t3;
    __syncthreads();   // hist zeros visible before atomics

    // ---- histogram pass straight from the in-flight registers ----
    {
        unsigned uu[16] = { t0.x, t0.y, t0.z, t0.w,  t1.x, t1.y, t1.z, t1.w,
                            t2.x, t2.y, t2.z, t2.w,  t3.x, t3.y, t3.z, t3.w };
#pragma unroll
        for (int e = 0; e < 16; e++) {
            int bin = min(bin_of(uu[e]), 255);
            if (bin >= 1) atomicAdd(&sm.hist[bin], 1u);   // flat predicated ATOMS
        }
    }
    __syncthreads();

    // ---- descending cumulative scan over 256 bins ----
    {
        int b = 255 - tid;
        unsigned cb = (b >= 1) ? sm.hist[b] : 0u;   // bin 0 uncounted by design
        unsigned incl = cb;
#pragma unroll
        for (int d = 1; d < 32; d <<= 1) {
            unsigned n = __shfl_up_sync(FULLMASK, incl, d);
            if (lane >= d) incl += n;
        }
        if (lane == 31) sm.wsum[wid] = incl;
        __syncthreads();
#pragma unroll
        for (int w = 0; w < NWARP - 1; w++)
            if (w < wid) incl += sm.wsum[w];
        unsigned excl = incl - cb;
        if (excl < KSEL && KSEL <= incl) { sm.sel = (unsigned)b; sm.r2 = KSEL - excl; }
    }
    __syncthreads();

    // ---- retrieval: re-read own words from smem; body ~never entered ----
    const int sel = (int)sm.sel;
#pragma unroll
    for (int j = 0; j < 4; j++) {
        uint4 v = sm.data[tid + j * 256];
        unsigned w4[4] = { v.x, v.y, v.z, v.w };
#pragma unroll
        for (int c = 0; c < 4; c++) {
            if (bin_of(w4[c]) == sel) {
                unsigned pos = atomicAdd(&sm.cnt, 1u);
                if (pos < (unsigned)CAP) {
                    sm.cs[pos]   = w4[c] << 1;   // 31-bit |x| key, order-preserving
                    sm.cinv[pos] = invbase - (unsigned)((j << 10) + c);
                }
            }
        }
    }
    __syncthreads();

    const bool fb = (sm.sel == 0xFFFFFFFFu) || (sm.sel >= 255u) || (sm.cnt > (unsigned)CAP);
    if (!fb) {
        // ---- exact selection of rank r2 within the bin (ties by index) ----
        const unsigned m2 = sm.cnt;
        const unsigned r2 = sm.r2;
        if ((unsigned)tid < m2) {
            unsigned si = sm.cs[tid], vi = sm.cinv[tid];
            unsigned rank = 0;
            for (unsigned j = 0; j < m2; j++) {
                unsigned sj = sm.cs[j], vj = sm.cinv[j];
                rank += (sj > si || (sj == si && vj > vi)) ? 1u : 0u;
            }
            if (rank == r2 - 1u) { sm.Ts = si; sm.inv_star = vi; }
        }
    } else {
        // ---- exact fallback: bitwise binary search (block-uniform, reads stash) ----
        unsigned lo = 0;                       // s values are even; bit0 skipped
        for (int bit = 31; bit >= 1; bit--) {
            unsigned T = lo | (1u << bit);
            unsigned c = 0;
            for (int j = 0; j < 4; j++) {
                uint4 v = sm.data[tid + j * 256];
                c += ((v.x << 1) >= T) + ((v.y << 1) >= T) + ((v.z << 1) >= T) + ((v.w << 1) >= T);
            }
            if (blk_total(&sm, c, lane, wid) >= KSEL) lo = T;
        }
        const unsigned Tsf = lo;               // exact KSEL-th largest key
        unsigned cgt = 0;
        for (int j = 0; j < 4; j++) {
            uint4 v = sm.data[tid + j * 256];
            cgt += ((v.x << 1) > Tsf) + ((v.y << 1) > Tsf) + ((v.z << 1) > Tsf) + ((v.w << 1) > Tsf);
        }
        cgt = blk_total(&sm, cgt, lane, wid);
        const unsigned req = KSEL - cgt;       // >= 1 by construction
        unsigned vlo = 0;
        for (int bit = 11; bit >= 0; bit--) {
            unsigned V = vlo | (1u << bit);
            unsigned c = 0;
            for (int j = 0; j < 4; j++) {
                uint4 v = sm.data[tid + j * 256];
                unsigned w4[4] = { v.x, v.y, v.z, v.w };
                for (int cc = 0; cc < 4; cc++) {
                    unsigned inv = invbase - (unsigned)((j << 10) + cc);
                    c += (((w4[cc] << 1) == Tsf) && inv >= V) ? 1u : 0u;
                }
            }
            if (blk_total(&sm, c, lane, wid) >= req) vlo = V;
        }
        if (tid == 0) { sm.Ts = Tsf; sm.inv_star = vlo; }
    }
    __syncthreads();

    const unsigned Ts    = sm.Ts;
    const unsigned istar = sm.inv_star;

    // ---- masked write-back from the smem stash ----
#pragma unroll
    for (int j = 0; j < 4; j++) {
        uint4 v = sm.data[tid + j * 256];
        unsigned w4[4] = { v.x, v.y, v.z, v.w };
        unsigned o[4];
#pragma unroll
        for (int c = 0; c < 4; c++) {
            const unsigned s   = w4[c] << 1;
            const unsigned inv = invbase - (unsigned)((j << 10) + c);
            const bool keep = (s > Ts) || (s == Ts && inv >= istar);
            o[c] = keep ? w4[c] : 0u;
        }
        uint4 ov; ov.x = o[0]; ov.y = o[1]; ov.z = o[2]; ov.w = o[3];
        yout[tid + j * 256] = ov;
    }
}

extern "C" void kernel_launch(void* const* d_in, const int* in_sizes, int n_in,
                              void* d_out, int out_size) {
    const float* x = (const float*)d_in[0];
    float* y = (float*)d_out;
    const int nrows = in_sizes[0] / HW;   // 16384 rows of 4096
    topk_sparse_kernel<<<nrows, NTHREAD>>>(x, y);
}

// round 6
// speedup vs baseline: 2.3473x; 1.0011x over previous
#include <cuda_runtime.h>
#include <cstdint>
#include <cstddef>

#define FULLMASK 0xFFFFFFFFu

namespace {
constexpr int      HW      = 4096;   // 64*64
constexpr unsigned KSEL    = 409;    // int(0.1 * 4096)
constexpr int      NTHREAD = 256;
constexpr int      NWARP   = 8;
constexpr int      CAP     = 64;     // candidate capacity for selected bin
// Integer bin over the magnitude key s = u<<1 (sign shifted out):
//   bin = (s >> 15) - BINBASE,  BINBASE = bits(1.5f)<<1 >> 15 = 65280.
// bin 0   <=> |x| in [1.5, 1.50098)  -- uncounted; ~6 sigma below threshold
// bin 255 <=> |x| >= 1.99902 via clamp -- if selected, exact fallback runs.
// Bin boundaries are exact in key space: membership test is s - slo < 2^15.
constexpr int      BINBASE = 65280;  // 0x7F800000 >> 15
}

struct SmemT {
    uint4    data[HW / 4];   // 16KB row stash (each thread reads only its own words)
    unsigned hist[256];
    unsigned wsum[NWARP];
    unsigned cnt;
    unsigned sel;       // selected bin (0xFFFFFFFF = none)
    unsigned r2;        // rank within selected bin
    unsigned Ts;        // threshold key (|x| bits << 1)
    unsigned inv_star;  // inverted-index cutoff for exact ties
    unsigned cs[CAP];
    unsigned cinv[CAP];
};

// Block-wide total of per-thread count c (broadcast). Fallback path only.
__device__ __forceinline__ unsigned blk_total(SmemT* sm, unsigned c, int lane, int wid) {
    c = __reduce_add_sync(FULLMASK, c);
    __syncthreads();               // protect wsum reuse across calls
    if (lane == 0) sm->wsum[wid] = c;
    __syncthreads();
    unsigned t = 0;
#pragma unroll
    for (int w = 0; w < NWARP; w++) t += sm->wsum[w];
    return t;
}

__global__ void __launch_bounds__(NTHREAD, 7)
topk_sparse_kernel(const float* __restrict__ x, float* __restrict__ y)
{
    __shared__ SmemT sm;
    const int tid  = threadIdx.x;
    const int lane = tid & 31;
    const int wid  = tid >> 5;
    const size_t rowbase = (size_t)blockIdx.x * (HW / 4);
    const uint4* xin  = reinterpret_cast<const uint4*>(x) + rowbase;
    uint4*       yout = reinterpret_cast<uint4*>(y) + rowbase;
    // element (j,c) at linear idx 4*tid + 1024*j + c; inv = 4095 - idx
    const unsigned invbase = 4095u - ((unsigned)tid << 2);

    // ---- load row (4 x LDG.128, front-batched for MLP), stash to smem ----
    uint4 t0 = xin[tid];
    uint4 t1 = xin[tid + 256];
    uint4 t2 = xin[tid + 512];
    uint4 t3 = xin[tid + 768];

    sm.hist[tid] = 0;
    if (tid == 0) { sm.cnt = 0; sm.sel = 0xFFFFFFFFu; }

    sm.data[tid]       = t0;
    sm.data[tid + 256] = t1;
    sm.data[tid + 512] = t2;
    sm.data[tid + 768] = t3;
    __syncthreads();   // hist zeros visible before atomics

    // ---- histogram pass straight from the in-flight registers ----
    {
        unsigned uu[16] = { t0.x, t0.y, t0.z, t0.w,  t1.x, t1.y, t1.z, t1.w,
                            t2.x, t2.y, t2.z, t2.w,  t3.x, t3.y, t3.z, t3.w };
#pragma unroll
        for (int e = 0; e < 16; e++) {
            int b = (int)((uu[e] << 1) >> 15) - BINBASE;
            b = min(b, 255);
            if (b >= 1) atomicAdd(&sm.hist[b], 1u);   // flat predicated ATOMS
        }
    }
    __syncthreads();

    // ---- descending cumulative scan over 256 bins ----
    {
        int b = 255 - tid;
        unsigned cb = (b >= 1) ? sm.hist[b] : 0u;   // bin 0 uncounted by design
        unsigned incl = cb;
#pragma unroll
        for (int d = 1; d < 32; d <<= 1) {
            unsigned n = __shfl_up_sync(FULLMASK, incl, d);
            if (lane >= d) incl += n;
        }
        if (lane == 31) sm.wsum[wid] = incl;
        __syncthreads();
#pragma unroll
        for (int w = 0; w < NWARP - 1; w++)
            if (w < wid) incl += sm.wsum[w];
        unsigned excl = incl - cb;
        if (excl < KSEL && KSEL <= incl) { sm.sel = (unsigned)b; sm.r2 = KSEL - excl; }
    }
    __syncthreads();

    // ---- retrieval: 2-op range test against the selected bin's key range ----
    // (if sel is invalid, pushes are garbage but fb is taken and they're unused)
    const unsigned slo = (sm.sel + (unsigned)BINBASE) << 15;
#pragma unroll
    for (int j = 0; j < 4; j++) {
        uint4 v = sm.data[tid + j * 256];
        unsigned w4[4] = { v.x, v.y, v.z, v.w };
#pragma unroll
        for (int c = 0; c < 4; c++) {
            unsigned s = w4[c] << 1;
            if (s - slo < (1u << 15)) {            // exact bin membership
                unsigned pos = atomicAdd(&sm.cnt, 1u);
                if (pos < (unsigned)CAP) {
                    sm.cs[pos]   = s;
                    sm.cinv[pos] = invbase - (unsigned)((j << 10) + c);
                }
            }
        }
    }
    __syncthreads();

    const bool fb = (sm.sel == 0xFFFFFFFFu) || (sm.sel >= 255u) || (sm.cnt > (unsigned)CAP);
    if (!fb) {
        // ---- exact selection of rank r2 within the bin (ties by index) ----
        const unsigned m2 = sm.cnt;
        const unsigned r2 = sm.r2;
        if ((unsigned)tid < m2) {
            unsigned si = sm.cs[tid], vi = sm.cinv[tid];
            unsigned rank = 0;
            for (unsigned j = 0; j < m2; j++) {
                unsigned sj = sm.cs[j], vj = sm.cinv[j];
                rank += (sj > si || (sj == si && vj > vi)) ? 1u : 0u;
            }
            if (rank == r2 - 1u) { sm.Ts = si; sm.inv_star = vi; }
        }
    } else {
        // ---- exact fallback: bitwise binary search (block-uniform, reads stash) ----
        unsigned lo = 0;                       // s values are even; bit0 skipped
        for (int bit = 31; bit >= 1; bit--) {
            unsigned T = lo | (1u << bit);
            unsigned c = 0;
            for (int j = 0; j < 4; j++) {
                uint4 v = sm.data[tid + j * 256];
                c += ((v.x << 1) >= T) + ((v.y << 1) >= T) + ((v.z << 1) >= T) + ((v.w << 1) >= T);
            }
            if (blk_total(&sm, c, lane, wid) >= KSEL) lo = T;
        }
        const unsigned Tsf = lo;               // exact KSEL-th largest key
        unsigned cgt = 0;
        for (int j = 0; j < 4; j++) {
            uint4 v = sm.data[tid + j * 256];
            cgt += ((v.x << 1) > Tsf) + ((v.y << 1) > Tsf) + ((v.z << 1) > Tsf) + ((v.w << 1) > Tsf);
        }
        cgt = blk_total(&sm, cgt, lane, wid);
        const unsigned req = KSEL - cgt;       // >= 1 by construction
        unsigned vlo = 0;
        for (int bit = 11; bit >= 0; bit--) {
            unsigned V = vlo | (1u << bit);
            unsigned c = 0;
            for (int j = 0; j < 4; j++) {
                uint4 v = sm.data[tid + j * 256];
                unsigned w4[4] = { v.x, v.y, v.z, v.w };
                for (int cc = 0; cc < 4; cc++) {
                    unsigned inv = invbase - (unsigned)((j << 10) + cc);
                    c += (((w4[cc] << 1) == Tsf) && inv >= V) ? 1u : 0u;
                }
            }
            if (blk_total(&sm, c, lane, wid) >= req) vlo = V;
        }
        if (tid == 0) { sm.Ts = Tsf; sm.inv_star = vlo; }
    }
    __syncthreads();

    const unsigned Ts    = sm.Ts;
    const unsigned istar = sm.inv_star;

    // ---- masked write-back from the smem stash ----
#pragma unroll
    for (int j = 0; j < 4; j++) {
        uint4 v = sm.data[tid + j * 256];
        unsigned w4[4] = { v.x, v.y, v.z, v.w };
        unsigned o[4];
#pragma unroll
        for (int c = 0; c < 4; c++) {
            const unsigned s   = w4[c] << 1;
            const unsigned inv = invbase - (unsigned)((j << 10) + c);
            const bool keep = (s > Ts) || (s == Ts && inv >= istar);
            o[c] = keep ? w4[c] : 0u;
        }
        uint4 ov; ov.x = o[0]; ov.y = o[1]; ov.z = o[2]; ov.w = o[3];
        yout[tid + j * 256] = ov;
    }
}

extern "C" void kernel_launch(void* const* d_in, const int* in_sizes, int n_in,
                              void* d_out, int out_size) {
    const float* x = (const float*)d_in[0];
    float* y = (float*)d_out;
    const int nrows = in_sizes[0] / HW;   // 16384 rows of 4096
    topk_sparse_kernel<<<nrows, NTHREAD>>>(x, y);
}